// round 1
// baseline (speedup 1.0000x reference)
#include <cuda_runtime.h>

#define BB 16
#define CC 64
#define HH 128
#define WW 128
#define HWD (HH*WW)            // 16384
#define CHW (CC*HWD)           // 1048576
#define NELEM (BB*CHW)         // 16777216
#define NGRP (BB*CC)           // 1024
#define WSZ (BB*CC*CC*9)       // 589824

// Scratch (device globals: allocation-free rule)
__device__ float g_buf1[NELEM];
__device__ float g_buf2[NELEM];
__device__ float g_w1t[WSZ];
__device__ float g_w2t[WSZ];
__device__ float g_mean[NGRP];
__device__ float g_rstd[NGRP];

// ---------- packed f32x2 helpers ----------
__device__ __forceinline__ unsigned long long pk2(float lo, float hi) {
    unsigned long long r;
    asm("mov.b64 %0, {%1, %2};" : "=l"(r) : "f"(lo), "f"(hi));
    return r;
}
__device__ __forceinline__ void fma2(unsigned long long& d, unsigned long long a, unsigned long long b) {
    asm("fma.rn.f32x2 %0, %1, %2, %0;" : "+l"(d) : "l"(a), "l"(b));
}
__device__ __forceinline__ float2 upk2(unsigned long long p) {
    float2 f;
    asm("mov.b64 {%0, %1}, %2;" : "=f"(f.x), "=f"(f.y) : "l"(p));
    return f;
}

// ---------- weight transpose: [b][co][ci][3][3] -> [b][ci][k][co] ----------
template<int PASS>
__global__ void transpose_w_kernel(const float* __restrict__ src) {
    float* dst = (PASS == 0) ? g_w1t : g_w2t;
    int i = blockIdx.x * 256 + threadIdx.x;
    if (i >= WSZ) return;
    int co = i & 63;
    int t  = i >> 6;
    int k  = t % 9; t /= 9;
    int ci = t & 63;
    int b  = t >> 6;
    dst[i] = src[(((b * 64 + co) * 64 + ci) * 9) + k];
}

// ---------- dynamic grouped 3x3 conv, pad 1 ----------
// Block: 16x16 spatial tile, all 64 output channels, 256 threads.
// Thread: 4 adjacent pixels (2 f32x2 pairs) x 16 output channels.
template<int PASS>
__global__ __launch_bounds__(256, 2)
void conv_kernel(const float* __restrict__ x_ext) {
    const float* xin = (PASS == 0) ? x_ext : g_buf1;
    const float* wt  = (PASS == 0) ? g_w1t : g_w2t;
    float* yout      = (PASS == 0) ? g_buf1 : g_buf2;

    const int bx = blockIdx.x, by = blockIdx.y, b = blockIdx.z;
    const int tid = threadIdx.x;
    const int cg = tid >> 6;          // 0..3
    const int co_base = cg << 4;      // 0,16,32,48
    const int slot = tid & 63;
    const int r  = slot >> 2;         // 0..15 (row in tile)
    const int c4 = (slot & 3) << 2;   // 0,4,8,12 (col base in tile)

    __shared__ float s_in[18][20];
    __shared__ unsigned long long s_w[9][64];   // duplicated pairs {w,w}

    unsigned long long accA[16], accB[16];
#pragma unroll
    for (int j = 0; j < 16; ++j) { accA[j] = 0ull; accB[j] = 0ull; }

    const float* xb = xin + (size_t)b * CHW;
    const float* wb = wt  + (size_t)b * (CC * CC * 9);
    const int y0 = by * 16, x0 = bx * 16;

    for (int ci = 0; ci < 64; ++ci) {
        // stage input tile 18x18 (with zero halo)
        const float* xc = xb + ci * HWD;
        for (int i = tid; i < 18 * 18; i += 256) {
            int rr = i / 18, cc = i - rr * 18;
            int gy = y0 + rr - 1, gx = x0 + cc - 1;
            float v = 0.f;
            if ((unsigned)gy < 128u && (unsigned)gx < 128u) v = __ldg(xc + gy * 128 + gx);
            s_in[rr][cc] = v;
        }
        // stage weights for this ci: 576 contiguous floats [k][co], duplicated
        const float* wc = wb + ci * 576;
        for (int i = tid; i < 576; i += 256) {
            float wv = __ldg(wc + i);
            ((unsigned long long*)s_w)[i] = pk2(wv, wv);
        }
        __syncthreads();

        // build 9 input pairs per pixel-pair from 3x6 window
        unsigned long long pa[9], pb[9];
#pragma unroll
        for (int kh = 0; kh < 3; ++kh) {
            float v0 = s_in[r + kh][c4 + 0];
            float v1 = s_in[r + kh][c4 + 1];
            float v2 = s_in[r + kh][c4 + 2];
            float v3 = s_in[r + kh][c4 + 3];
            float v4 = s_in[r + kh][c4 + 4];
            float v5 = s_in[r + kh][c4 + 5];
            pa[kh * 3 + 0] = pk2(v0, v1);  pb[kh * 3 + 0] = pk2(v2, v3);
            pa[kh * 3 + 1] = pk2(v1, v2);  pb[kh * 3 + 1] = pk2(v3, v4);
            pa[kh * 3 + 2] = pk2(v2, v3);  pb[kh * 3 + 2] = pk2(v4, v5);
        }

        // 288 FFMA2 + 144 LDS.64 (broadcast) per ci
#pragma unroll
        for (int k = 0; k < 9; ++k) {
#pragma unroll
            for (int j = 0; j < 16; ++j) {
                unsigned long long wv = s_w[k][co_base + j];
                fma2(accA[j], pa[k], wv);
                fma2(accB[j], pb[k], wv);
            }
        }
        __syncthreads();
    }

    // epilogue: 16 x STG.128
    float* yb = yout + (size_t)b * CHW;
    const int oy = y0 + r, ox = x0 + c4;
#pragma unroll
    for (int j = 0; j < 16; ++j) {
        float2 a = upk2(accA[j]);
        float2 c = upk2(accB[j]);
        float4 o; o.x = a.x; o.y = a.y; o.z = c.x; o.w = c.y;
        *(float4*)(yb + (size_t)(co_base + j) * HWD + oy * 128 + ox) = o;
    }
}

// ---------- per (b,c) instance-norm statistics ----------
template<int PASS>
__global__ void stats_kernel() {
    const float* buf = (PASS == 0) ? g_buf1 : g_buf2;
    const int g = blockIdx.x;
    const float4* p = (const float4*)(buf + (size_t)g * HWD);
    float s = 0.f, s2 = 0.f;
    for (int i = threadIdx.x; i < HWD / 4; i += 256) {
        float4 v = p[i];
        s  += v.x + v.y + v.z + v.w;
        s2 += v.x * v.x + v.y * v.y + v.z * v.z + v.w * v.w;
    }
#pragma unroll
    for (int o = 16; o; o >>= 1) {
        s  += __shfl_xor_sync(0xffffffffu, s, o);
        s2 += __shfl_xor_sync(0xffffffffu, s2, o);
    }
    __shared__ float ss[8], ss2[8];
    int w = threadIdx.x >> 5, l = threadIdx.x & 31;
    if (l == 0) { ss[w] = s; ss2[w] = s2; }
    __syncthreads();
    if (threadIdx.x == 0) {
        float t = 0.f, t2 = 0.f;
#pragma unroll
        for (int i = 0; i < 8; ++i) { t += ss[i]; t2 += ss2[i]; }
        const float inv = 1.f / (float)HWD;
        float m = t * inv;
        float var = t2 * inv - m * m;
        g_mean[g] = m;
        g_rstd[g] = rsqrtf(var + 1e-5f);
    }
}

__device__ __forceinline__ float lrelu(float v) { return v >= 0.f ? v : 0.2f * v; }

// ---------- normalize + leaky relu (in place on buf1) ----------
__global__ void norm_lrelu_kernel() {
    const int i = blockIdx.x * 256 + threadIdx.x;      // float4 index
    float4 v = ((const float4*)g_buf1)[i];
    const int g = i >> 12;                              // 4096 float4 per group
    const float m = g_mean[g], rs = g_rstd[g];
    v.x = lrelu((v.x - m) * rs);
    v.y = lrelu((v.y - m) * rs);
    v.z = lrelu((v.z - m) * rs);
    v.w = lrelu((v.w - m) * rs);
    ((float4*)g_buf1)[i] = v;
}

// ---------- out = lrelu(x + IN(buf2)) ----------
__global__ void final_kernel(const float* __restrict__ x, float* __restrict__ out) {
    const int i = blockIdx.x * 256 + threadIdx.x;      // float4 index
    float4 v  = ((const float4*)g_buf2)[i];
    float4 xv = ((const float4*)x)[i];
    const int g = i >> 12;
    const float m = g_mean[g], rs = g_rstd[g];
    float4 o;
    o.x = lrelu(xv.x + (v.x - m) * rs);
    o.y = lrelu(xv.y + (v.y - m) * rs);
    o.z = lrelu(xv.z + (v.z - m) * rs);
    o.w = lrelu(xv.w + (v.w - m) * rs);
    ((float4*)out)[i] = o;
}

extern "C" void kernel_launch(void* const* d_in, const int* in_sizes, int n_in,
                              void* d_out, int out_size) {
    const float* x  = (const float*)d_in[0];
    const float* k1 = (const float*)d_in[1];
    const float* k2 = (const float*)d_in[2];
    float* out = (float*)d_out;

    const int tposeBlocks = (WSZ + 255) / 256;
    transpose_w_kernel<0><<<tposeBlocks, 256>>>(k1);
    transpose_w_kernel<1><<<tposeBlocks, 256>>>(k2);

    dim3 cgrid(WW / 16, HH / 16, BB);
    conv_kernel<0><<<cgrid, 256>>>(x);
    stats_kernel<0><<<NGRP, 256>>>();
    norm_lrelu_kernel<<<NELEM / 1024, 256>>>();

    conv_kernel<1><<<cgrid, 256>>>(x);
    stats_kernel<1><<<NGRP, 256>>>();
    final_kernel<<<NELEM / 1024, 256>>>(x, out);
}

// round 2
// speedup vs baseline: 1.3514x; 1.3514x over previous
#include <cuda_runtime.h>

#define BB 16
#define CC 64
#define HH 128
#define WW 128
#define HWD (HH*WW)            // 16384
#define CHW (CC*HWD)           // 1048576
#define NELEM (BB*CHW)         // 16777216
#define NGRP (BB*CC)           // 1024
#define WSZ (BB*CC*CC*9)       // 589824

// Scratch (device globals: allocation-free rule)
__device__ float g_buf1[NELEM];
__device__ float g_buf2[NELEM];
__device__ float g_w1t[WSZ];
__device__ float g_w2t[WSZ];
__device__ float g_mean[NGRP];
__device__ float g_rstd[NGRP];

// ---------- packed f32x2 helpers ----------
__device__ __forceinline__ unsigned long long pk2(float lo, float hi) {
    unsigned long long r;
    asm("mov.b64 %0, {%1, %2};" : "=l"(r) : "f"(lo), "f"(hi));
    return r;
}
__device__ __forceinline__ void fma2(unsigned long long& d, unsigned long long a, unsigned long long b) {
    asm("fma.rn.f32x2 %0, %1, %2, %0;" : "+l"(d) : "l"(a), "l"(b));
}
__device__ __forceinline__ float2 upk2(unsigned long long p) {
    float2 f;
    asm("mov.b64 {%0, %1}, %2;" : "=f"(f.x), "=f"(f.y) : "l"(p));
    return f;
}

// ---------- weight transpose (both kernels): [b][co][ci][3][3] -> [b][ci][k][co]
__global__ void transpose_w_kernel(const float* __restrict__ k1,
                                   const float* __restrict__ k2) {
    int gi = blockIdx.x * 256 + threadIdx.x;
    if (gi >= 2 * WSZ) return;
    const float* src = (gi < WSZ) ? k1 : k2;
    float* dst       = (gi < WSZ) ? g_w1t : g_w2t;
    int i = (gi < WSZ) ? gi : gi - WSZ;
    int co = i & 63;
    int t  = i >> 6;
    int k  = t % 9; t /= 9;
    int ci = t & 63;
    int b  = t >> 6;
    dst[i] = src[(((b * 64 + co) * 64 + ci) * 9) + k];
}

// ---------- dynamic grouped 3x3 conv, pad 1, software-pipelined ----------
// Block: 16x16 spatial tile, all 64 output channels, 256 threads.
// Thread: 4 adjacent pixels (2 f32x2 pairs) x 16 output channels.
#define SROW 19
template<int PASS>
__global__ __launch_bounds__(256, 2)
void conv_kernel(const float* __restrict__ x_ext) {
    const float* xin = (PASS == 0) ? x_ext : g_buf1;
    const float* wt  = (PASS == 0) ? g_w1t : g_w2t;
    float* yout      = (PASS == 0) ? g_buf1 : g_buf2;

    const int bx = blockIdx.x, by = blockIdx.y, b = blockIdx.z;
    const int tid = threadIdx.x;
    const int co_base = (tid >> 6) << 4;   // 0,16,32,48
    const int slot = tid & 63;
    const int r  = slot >> 2;              // 0..15
    const int c4 = (slot & 3) << 2;        // 0,4,8,12

    __shared__ float s_in[2][18][SROW];
    __shared__ unsigned long long s_w[2][576];

    const float* xb = xin + (size_t)b * CHW;
    const float* wb = wt  + (size_t)b * (CC * CC * 9);
    const int y0 = by * 16, x0 = bx * 16;

    // ---- loop-invariant staging coords: input elems tid and tid+256 (<324)
    const int rr0 = tid / 18, cc0 = tid - rr0 * 18;
    const int gy0 = y0 + rr0 - 1, gx0 = x0 + cc0 - 1;
    const bool v0 = ((unsigned)gy0 < 128u) && ((unsigned)gx0 < 128u);
    const int off0 = gy0 * 128 + gx0;
    const int e1 = tid + 256;
    const int rr1 = e1 / 18, cc1 = e1 - rr1 * 18;
    const bool has1 = e1 < 324;
    const int gy1 = y0 + rr1 - 1, gx1 = x0 + cc1 - 1;
    const bool v1 = has1 && ((unsigned)gy1 < 128u) && ((unsigned)gx1 < 128u);
    const int off1 = gy1 * 128 + gx1;
    const bool hw2 = tid < 64;             // weight elem tid+512 (<576)

    unsigned long long accA[16], accB[16];
#pragma unroll
    for (int j = 0; j < 16; ++j) { accA[j] = 0ull; accB[j] = 0ull; }

    // ---- prologue: stage ci = 0 into buffer 0
    {
        float i0 = v0 ? __ldg(xb + off0) : 0.f;
        float i1 = v1 ? __ldg(xb + off1) : 0.f;
        float w0 = __ldg(wb + tid);
        float w1 = __ldg(wb + tid + 256);
        float w2 = hw2 ? __ldg(wb + tid + 512) : 0.f;
        s_in[0][rr0][cc0] = i0;
        if (has1) s_in[0][rr1][cc1] = i1;
        s_w[0][tid] = pk2(w0, w0);
        s_w[0][tid + 256] = pk2(w1, w1);
        if (hw2) s_w[0][tid + 512] = pk2(w2, w2);
    }

    for (int ci = 0; ci < 64; ++ci) {
        __syncthreads();   // buf[ci&1] staged; buf[(ci+1)&1] free (read in ci-1)
        const int cur = ci & 1, nxt = cur ^ 1;

        // prefetch ci+1 into registers (latency hidden by compute below)
        float ni0 = 0.f, ni1 = 0.f, nw0 = 0.f, nw1 = 0.f, nw2 = 0.f;
        if (ci < 63) {
            const float* xc = xb + (ci + 1) * HWD;
            const float* wc = wb + (ci + 1) * 576;
            ni0 = v0 ? __ldg(xc + off0) : 0.f;
            ni1 = v1 ? __ldg(xc + off1) : 0.f;
            nw0 = __ldg(wc + tid);
            nw1 = __ldg(wc + tid + 256);
            nw2 = hw2 ? __ldg(wc + tid + 512) : 0.f;
        }

        // compute current ci: 288 FFMA2 + 144 LDS.64(broadcast)
#pragma unroll
        for (int kh = 0; kh < 3; ++kh) {
            float u0 = s_in[cur][r + kh][c4 + 0];
            float u1 = s_in[cur][r + kh][c4 + 1];
            float u2 = s_in[cur][r + kh][c4 + 2];
            float u3 = s_in[cur][r + kh][c4 + 3];
            float u4 = s_in[cur][r + kh][c4 + 4];
            float u5 = s_in[cur][r + kh][c4 + 5];
            unsigned long long pA0 = pk2(u0, u1), pB0 = pk2(u2, u3);
            unsigned long long pA1 = pk2(u1, u2), pB1 = pk2(u3, u4);
            unsigned long long pA2 = pk2(u2, u3), pB2 = pk2(u4, u5);
#pragma unroll
            for (int j = 0; j < 16; ++j) {
                unsigned long long w0v = s_w[cur][(kh * 3 + 0) * 64 + co_base + j];
                fma2(accA[j], pA0, w0v);
                fma2(accB[j], pB0, w0v);
                unsigned long long w1v = s_w[cur][(kh * 3 + 1) * 64 + co_base + j];
                fma2(accA[j], pA1, w1v);
                fma2(accB[j], pB1, w1v);
                unsigned long long w2v = s_w[cur][(kh * 3 + 2) * 64 + co_base + j];
                fma2(accA[j], pA2, w2v);
                fma2(accB[j], pB2, w2v);
            }
        }

        // stage ci+1 into the other buffer (safe: all warps past sync(ci))
        if (ci < 63) {
            s_in[nxt][rr0][cc0] = ni0;
            if (has1) s_in[nxt][rr1][cc1] = ni1;
            s_w[nxt][tid] = pk2(nw0, nw0);
            s_w[nxt][tid + 256] = pk2(nw1, nw1);
            if (hw2) s_w[nxt][tid + 512] = pk2(nw2, nw2);
        }
    }

    // epilogue: 16 x STG.128
    float* yb = yout + (size_t)b * CHW;
    const int oy = y0 + r, ox = x0 + c4;
#pragma unroll
    for (int j = 0; j < 16; ++j) {
        float2 a = upk2(accA[j]);
        float2 c = upk2(accB[j]);
        float4 o; o.x = a.x; o.y = a.y; o.z = c.x; o.w = c.y;
        *(float4*)(yb + (size_t)(co_base + j) * HWD + oy * 128 + ox) = o;
    }
}

// ---------- per (b,c) instance-norm statistics ----------
template<int PASS>
__global__ void stats_kernel() {
    const float* buf = (PASS == 0) ? g_buf1 : g_buf2;
    const int g = blockIdx.x;
    const float4* p = (const float4*)(buf + (size_t)g * HWD);
    float s = 0.f, s2 = 0.f;
    for (int i = threadIdx.x; i < HWD / 4; i += 256) {
        float4 v = p[i];
        s  += v.x + v.y + v.z + v.w;
        s2 += v.x * v.x + v.y * v.y + v.z * v.z + v.w * v.w;
    }
#pragma unroll
    for (int o = 16; o; o >>= 1) {
        s  += __shfl_xor_sync(0xffffffffu, s, o);
        s2 += __shfl_xor_sync(0xffffffffu, s2, o);
    }
    __shared__ float ss[8], ss2[8];
    int w = threadIdx.x >> 5, l = threadIdx.x & 31;
    if (l == 0) { ss[w] = s; ss2[w] = s2; }
    __syncthreads();
    if (threadIdx.x == 0) {
        float t = 0.f, t2 = 0.f;
#pragma unroll
        for (int i = 0; i < 8; ++i) { t += ss[i]; t2 += ss2[i]; }
        const float inv = 1.f / (float)HWD;
        float m = t * inv;
        float var = t2 * inv - m * m;
        g_mean[g] = m;
        g_rstd[g] = rsqrtf(var + 1e-5f);
    }
}

__device__ __forceinline__ float lrelu(float v) { return v >= 0.f ? v : 0.2f * v; }

// ---------- normalize + leaky relu (in place on buf1) ----------
__global__ void norm_lrelu_kernel() {
    const int i = blockIdx.x * 256 + threadIdx.x;      // float4 index
    float4 v = ((const float4*)g_buf1)[i];
    const int g = i >> 12;                              // 4096 float4 per group
    const float m = g_mean[g], rs = g_rstd[g];
    v.x = lrelu((v.x - m) * rs);
    v.y = lrelu((v.y - m) * rs);
    v.z = lrelu((v.z - m) * rs);
    v.w = lrelu((v.w - m) * rs);
    ((float4*)g_buf1)[i] = v;
}

// ---------- out = lrelu(x + IN(buf2)) ----------
__global__ void final_kernel(const float* __restrict__ x, float* __restrict__ out) {
    const int i = blockIdx.x * 256 + threadIdx.x;      // float4 index
    float4 v  = ((const float4*)g_buf2)[i];
    float4 xv = ((const float4*)x)[i];
    const int g = i >> 12;
    const float m = g_mean[g], rs = g_rstd[g];
    float4 o;
    o.x = lrelu(xv.x + (v.x - m) * rs);
    o.y = lrelu(xv.y + (v.y - m) * rs);
    o.z = lrelu(xv.z + (v.z - m) * rs);
    o.w = lrelu(xv.w + (v.w - m) * rs);
    ((float4*)out)[i] = o;
}

extern "C" void kernel_launch(void* const* d_in, const int* in_sizes, int n_in,
                              void* d_out, int out_size) {
    const float* x  = (const float*)d_in[0];
    const float* k1 = (const float*)d_in[1];
    const float* k2 = (const float*)d_in[2];
    float* out = (float*)d_out;

    transpose_w_kernel<<<(2 * WSZ + 255) / 256, 256>>>(k1, k2);

    dim3 cgrid(WW / 16, HH / 16, BB);
    conv_kernel<0><<<cgrid, 256>>>(x);
    stats_kernel<0><<<NGRP, 256>>>();
    norm_lrelu_kernel<<<NELEM / 1024, 256>>>();

    conv_kernel<1><<<cgrid, 256>>>(x);
    stats_kernel<1><<<NGRP, 256>>>();
    final_kernel<<<NELEM / 1024, 256>>>(x, out);
}

// round 4
// speedup vs baseline: 2.3950x; 1.7722x over previous
#include <cuda_runtime.h>
#include <cuda_bf16.h>
#include <cstdint>

#define BB 16
#define CC 64
#define HH 128
#define WW 128
#define HWD (HH*WW)            // 16384
#define CHW (CC*HWD)           // 1048576
#define NELEM (BB*CHW)         // 16777216
#define NGRP (BB*CC)           // 1024
#define WSZ (BB*CC*CC*9)       // 589824

// Scratch (device globals: allocation-free rule)
__device__ float g_buf1[NELEM];
__device__ float g_buf2[NELEM];
__device__ __align__(16) __nv_bfloat16 g_w1h[WSZ];
__device__ __align__(16) __nv_bfloat16 g_w1l[WSZ];
__device__ __align__(16) __nv_bfloat16 g_w2h[WSZ];
__device__ __align__(16) __nv_bfloat16 g_w2l[WSZ];
__device__ float g_mean[NGRP];
__device__ float g_rstd[NGRP];

// ======================= PTX helpers (plain compute_103-safe) ==========
__device__ __forceinline__ uint32_t smem_u32(const void* p) {
    uint32_t a;
    asm("{ .reg .u64 t; cvta.to.shared.u64 t, %1; cvt.u32.u64 %0, t; }" : "=r"(a) : "l"(p));
    return a;
}
#define STS128(r0, r1, r2, r3, addr) \
    asm volatile("st.shared.v4.b32 [%0], {%1, %2, %3, %4};" \
        :: "r"(addr), "r"(r0), "r"(r1), "r"(r2), "r"(r3) : "memory")
#define LDSM4(r, addr) \
    asm volatile("ldmatrix.sync.aligned.m8n8.x4.shared.b16 {%0,%1,%2,%3}, [%4];" \
        : "=r"((r)[0]), "=r"((r)[1]), "=r"((r)[2]), "=r"((r)[3]) : "r"(addr))
#define MMA_BF16(d, a, b0, b1) \
    asm volatile("mma.sync.aligned.m16n8k16.row.col.f32.bf16.bf16.f32 " \
        "{%0,%1,%2,%3}, {%4,%5,%6,%7}, {%8,%9}, {%0,%1,%2,%3};" \
        : "+f"((d)[0]), "+f"((d)[1]), "+f"((d)[2]), "+f"((d)[3]) \
        : "r"((a)[0]), "r"((a)[1]), "r"((a)[2]), "r"((a)[3]), "r"(b0), "r"(b1))
#define CP_ASYNC16(dst, src) \
    asm volatile("cp.async.cg.shared.global [%0], [%1], 16;" :: "r"(dst), "l"(src) : "memory")
#define CP_COMMIT() asm volatile("cp.async.commit_group;" ::: "memory")
#define CP_WAIT(n)  asm volatile("cp.async.wait_group %0;" :: "n"(n) : "memory")
#define SWZ128(off) ((uint32_t)(off) ^ ((((uint32_t)(off)) >> 3) & 0x70u))

// ---- dynamic smem layout (bytes) ----
// A: [part(2)][khrow(3)] planes of 130x64 bf16 (SW128, padded to 17408 B)
// B: [buf(2)][kw(3)][part(2)] tiles of 64co x 64ci bf16 (SW128, 8192 B)
#define PLANE 17408
#define SMA_OFF 0
#define SMB_OFF 104448
#define SMB_BUF 49152
#define SMEM_TOTAL 202752

// ======================= weight prep: fp32 -> split bf16 ================
// dst layout: [b][tap(kh*3+kw)][co][ci]
__global__ void prep_w_kernel(const float* __restrict__ k1, const float* __restrict__ k2) {
    int gi = blockIdx.x * 256 + threadIdx.x;
    if (gi >= 2 * WSZ) return;
    const float* src; __nv_bfloat16 *dh, *dl; int i;
    if (gi < WSZ) { src = k1; dh = g_w1h; dl = g_w1l; i = gi; }
    else          { src = k2; dh = g_w2h; dl = g_w2l; i = gi - WSZ; }
    int ci = i & 63;
    int co = (i >> 6) & 63;
    int k9 = (i >> 12) % 9;
    int b  = (i >> 12) / 9;
    float w = src[(((b * 64 + co) * 64 + ci) * 9) + k9];
    __nv_bfloat16 h = __float2bfloat16(w);
    __nv_bfloat16 l = __float2bfloat16(w - __bfloat162float(h));
    dh[i] = h; dl[i] = l;
}

// ======================= conv via mma.sync bf16 split ===================
// CTA = (row y, batch b). M=128 px, N=64 co. kw shift folded into A-frag row.
template<int PASS>
__global__ __launch_bounds__(256, 1)
void conv_mma_kernel(const float* __restrict__ x_ext) {
    extern __shared__ __align__(1024) char smem[];
    const uint32_t sb = smem_u32(smem);
    const int tid = threadIdx.x, lid = tid & 31, wid = tid >> 5;
    const int y = blockIdx.x, b = blockIdx.y;
    const float* src = (PASS == 0) ? x_ext : g_buf1;
    const __nv_bfloat16* wh = (PASS == 0) ? g_w1h : g_w2h;
    const __nv_bfloat16* wl = (PASS == 0) ? g_w1l : g_w2l;
    float* dst = (PASS == 0) ? g_buf1 : g_buf2;

    // ---------- stage A: 3 kh-rows x 130 px x 64 ci, hi+lo ----------
    {
        const int px = tid & 127;
        const int cihalf = (tid >> 7) * 32;
        const int ar = px + 1;
#pragma unroll
        for (int krow = 0; krow < 3; ++krow) {
            const int grow = y + krow - 1;
            const bool vr = (unsigned)grow < 128u;
            const float* base = src + (size_t)b * CHW + (size_t)(vr ? grow : 0) * WW + px;
            const uint32_t ph = sb + SMA_OFF + (0 * 3 + krow) * PLANE;
            const uint32_t pl = sb + SMA_OFF + (1 * 3 + krow) * PLANE;
#pragma unroll
            for (int c8 = 0; c8 < 4; ++c8) {
                const int ci0 = cihalf + c8 * 8;
                float v[8];
#pragma unroll
                for (int j = 0; j < 8; ++j) {
                    float t = vr ? __ldg(base + (size_t)(ci0 + j) * HWD) : 0.f;
                    if (PASS == 1 && vr) {
                        const int g = b * 64 + ci0 + j;
                        t = (t - __ldg(g_mean + g)) * __ldg(g_rstd + g);
                        t = t >= 0.f ? t : 0.2f * t;
                    }
                    v[j] = t;
                }
                uint32_t hp[4], lp[4];
#pragma unroll
                for (int j = 0; j < 4; ++j) {
                    __nv_bfloat16 h0 = __float2bfloat16(v[2*j]);
                    __nv_bfloat16 h1 = __float2bfloat16(v[2*j+1]);
                    __nv_bfloat16 l0 = __float2bfloat16(v[2*j]   - __bfloat162float(h0));
                    __nv_bfloat16 l1 = __float2bfloat16(v[2*j+1] - __bfloat162float(h1));
                    hp[j] = (uint32_t)__bfloat16_as_ushort(h0) | ((uint32_t)__bfloat16_as_ushort(h1) << 16);
                    lp[j] = (uint32_t)__bfloat16_as_ushort(l0) | ((uint32_t)__bfloat16_as_ushort(l1) << 16);
                }
                const uint32_t off = SWZ128(ar * 128 + ci0 * 2);
                STS128(hp[0], hp[1], hp[2], hp[3], ph + off);
                STS128(lp[0], lp[1], lp[2], lp[3], pl + off);
            }
        }
        // zero halo rows ar=0 and ar=129 of all 6 planes
        if (tid < 96) {
            const int plane = tid >> 4;
            const int row = (tid & 8) ? 129 : 0;
            const int chunk = tid & 7;
            const uint32_t off = SWZ128(row * 128 + chunk * 16);
            STS128(0u, 0u, 0u, 0u, sb + SMA_OFF + plane * PLANE + off);
        }
    }

    // ---------- B staging via cp.async (double-buffered per kh) ----------
    auto issueB = [&](int kh, int buf) {
        const uint32_t dbase = sb + SMB_OFF + buf * SMB_BUF;
#pragma unroll
        for (int kw = 0; kw < 3; ++kw) {
#pragma unroll
            for (int part = 0; part < 2; ++part) {
                const __nv_bfloat16* s = (part ? wl : wh) + (size_t)(b * 9 + kh * 3 + kw) * 4096;
                const uint32_t dstb = dbase + (kw * 2 + part) * 8192;
#pragma unroll
                for (int i = 0; i < 2; ++i) {
                    const int chunk = i * 256 + tid;          // 0..511 (16B units)
                    CP_ASYNC16(dstb + SWZ128(chunk * 16), s + chunk * 8);
                }
            }
        }
    };

    issueB(0, 0); CP_COMMIT();

    // ---------- warp tiling ----------
    const int m0 = (wid & 3) * 32;          // px base
    const int n0 = (wid >> 2) * 32;         // co base
    const int la_row = lid & 15;
    const int la_k   = (lid & 16) ? 8 : 0;  // ci sub-block
    const int lb_n   = (lid & 7) + ((lid & 16) ? 8 : 0);
    const int lb_k   = (lid & 8);

    float acc[2][4][4];
#pragma unroll
    for (int mt = 0; mt < 2; ++mt)
#pragma unroll
        for (int nt = 0; nt < 4; ++nt)
#pragma unroll
            for (int j = 0; j < 4; ++j) acc[mt][nt][j] = 0.f;

    for (int kh = 0; kh < 3; ++kh) {
        if (kh < 2) { issueB(kh + 1, (kh + 1) & 1); CP_COMMIT(); }
        if (kh < 2) { CP_WAIT(1); } else { CP_WAIT(0); }
        __syncthreads();
        const uint32_t bkh = sb + SMB_OFF + (kh & 1) * SMB_BUF;

        for (int term = 0; term < 3; ++term) {
            const int ap = (term == 1) ? 1 : 0;
            const int bp = (term == 2) ? 1 : 0;
            const uint32_t aplane = sb + SMA_OFF + (ap * 3 + kh) * PLANE;
#pragma unroll
            for (int kw = 0; kw < 3; ++kw) {
                const uint32_t btile = bkh + (kw * 2 + bp) * 8192;
#pragma unroll
                for (int kt = 0; kt < 4; ++kt) {
                    uint32_t af[2][4];
#pragma unroll
                    for (int mt = 0; mt < 2; ++mt) {
                        const uint32_t off = (uint32_t)((m0 + mt * 16 + la_row + kw) * 128
                                                        + (kt * 16 + la_k) * 2);
                        LDSM4(af[mt], aplane + SWZ128(off));
                    }
                    uint32_t bf[2][4];
#pragma unroll
                    for (int nt2 = 0; nt2 < 2; ++nt2) {
                        const uint32_t off = (uint32_t)((n0 + nt2 * 16 + lb_n) * 128
                                                        + (kt * 16 + lb_k) * 2);
                        LDSM4(bf[nt2], btile + SWZ128(off));
                    }
#pragma unroll
                    for (int mt = 0; mt < 2; ++mt) {
                        MMA_BF16(acc[mt][0], af[mt], bf[0][0], bf[0][1]);
                        MMA_BF16(acc[mt][1], af[mt], bf[0][2], bf[0][3]);
                        MMA_BF16(acc[mt][2], af[mt], bf[1][0], bf[1][1]);
                        MMA_BF16(acc[mt][3], af[mt], bf[1][2], bf[1][3]);
                    }
                }
            }
        }
        __syncthreads();   // done reading B[kh&1] before it is re-filled
    }

    // ---------- epilogue: acc -> smem [co][132] -> coalesced gmem ----------
    float* D = (float*)(smem + SMB_OFF);
    {
        const int pr = lid >> 2, qc = 2 * (lid & 3);
#pragma unroll
        for (int mt = 0; mt < 2; ++mt) {
#pragma unroll
            for (int nt = 0; nt < 4; ++nt) {
                const int px = m0 + mt * 16 + pr;
                const int co = n0 + nt * 8 + qc;
                D[co * 132 + px]           = acc[mt][nt][0];
                D[(co + 1) * 132 + px]     = acc[mt][nt][1];
                D[co * 132 + px + 8]       = acc[mt][nt][2];
                D[(co + 1) * 132 + px + 8] = acc[mt][nt][3];
            }
        }
    }
    __syncthreads();
    {
        const int co = tid >> 2;
        const int pxb = (tid & 3) * 32;
        float* op = dst + (size_t)b * CHW + (size_t)co * HWD + y * WW + pxb;
#pragma unroll
        for (int i = 0; i < 8; ++i) {
            float4 v = *(float4*)&D[co * 132 + pxb + i * 4];
            *(float4*)(op + i * 4) = v;
        }
    }
}

// ======================= instance-norm stats =======================
template<int PASS>
__global__ void stats_kernel() {
    const float* buf = (PASS == 0) ? g_buf1 : g_buf2;
    const int g = blockIdx.x;
    const float4* p = (const float4*)(buf + (size_t)g * HWD);
    float s = 0.f, s2 = 0.f;
    for (int i = threadIdx.x; i < HWD / 4; i += 256) {
        float4 v = p[i];
        s  += v.x + v.y + v.z + v.w;
        s2 += v.x * v.x + v.y * v.y + v.z * v.z + v.w * v.w;
    }
#pragma unroll
    for (int o = 16; o; o >>= 1) {
        s  += __shfl_xor_sync(0xffffffffu, s, o);
        s2 += __shfl_xor_sync(0xffffffffu, s2, o);
    }
    __shared__ float ss[8], ss2[8];
    int w = threadIdx.x >> 5, l = threadIdx.x & 31;
    if (l == 0) { ss[w] = s; ss2[w] = s2; }
    __syncthreads();
    if (threadIdx.x == 0) {
        float t = 0.f, t2 = 0.f;
#pragma unroll
        for (int i = 0; i < 8; ++i) { t += ss[i]; t2 += ss2[i]; }
        const float inv = 1.f / (float)HWD;
        float m = t * inv;
        float var = t2 * inv - m * m;
        g_mean[g] = m;
        g_rstd[g] = rsqrtf(var + 1e-5f);
    }
}

__device__ __forceinline__ float lrelu(float v) { return v >= 0.f ? v : 0.2f * v; }

// ---------- out = lrelu(x + IN(buf2)) ----------
__global__ void final_kernel(const float* __restrict__ x, float* __restrict__ out) {
    const int i = blockIdx.x * 256 + threadIdx.x;      // float4 index
    float4 v  = ((const float4*)g_buf2)[i];
    float4 xv = ((const float4*)x)[i];
    const int g = i >> 12;
    const float m = g_mean[g], rs = g_rstd[g];
    float4 o;
    o.x = lrelu(xv.x + (v.x - m) * rs);
    o.y = lrelu(xv.y + (v.y - m) * rs);
    o.z = lrelu(xv.z + (v.z - m) * rs);
    o.w = lrelu(xv.w + (v.w - m) * rs);
    ((float4*)out)[i] = o;
}

extern "C" void kernel_launch(void* const* d_in, const int* in_sizes, int n_in,
                              void* d_out, int out_size) {
    const float* x  = (const float*)d_in[0];
    const float* k1 = (const float*)d_in[1];
    const float* k2 = (const float*)d_in[2];
    float* out = (float*)d_out;

    cudaFuncSetAttribute(conv_mma_kernel<0>, cudaFuncAttributeMaxDynamicSharedMemorySize, SMEM_TOTAL);
    cudaFuncSetAttribute(conv_mma_kernel<1>, cudaFuncAttributeMaxDynamicSharedMemorySize, SMEM_TOTAL);

    prep_w_kernel<<<(2 * WSZ + 255) / 256, 256>>>(k1, k2);

    dim3 grid(HH, BB);   // (row, batch)
    conv_mma_kernel<0><<<grid, 256, SMEM_TOTAL>>>(x);
    stats_kernel<0><<<NGRP, 256>>>();
    conv_mma_kernel<1><<<grid, 256, SMEM_TOTAL>>>(x);
    stats_kernel<1><<<NGRP, 256>>>();
    final_kernel<<<NELEM / 1024, 256>>>(x, out);
}

// round 5
// speedup vs baseline: 2.9858x; 1.2467x over previous
#include <cuda_runtime.h>
#include <cuda_bf16.h>
#include <cstdint>

#define BB 16
#define CC 64
#define HH 128
#define WW 128
#define HWD (HH*WW)            // 16384
#define CHW (CC*HWD)           // 1048576
#define NELEM (BB*CHW)         // 16777216
#define NGRP (BB*CC)           // 1024
#define WSZ (BB*CC*CC*9)       // 589824

// Scratch (device globals: allocation-free rule)
__device__ float g_buf1[NELEM];
__device__ float g_buf2[NELEM];
__device__ __align__(16) __nv_bfloat16 g_w1h[WSZ];
__device__ __align__(16) __nv_bfloat16 g_w1l[WSZ];
__device__ __align__(16) __nv_bfloat16 g_w2h[WSZ];
__device__ __align__(16) __nv_bfloat16 g_w2l[WSZ];
__device__ float g_mean[NGRP];
__device__ float g_rstd[NGRP];

// ======================= PTX helpers (plain compute_103-safe) ==========
__device__ __forceinline__ uint32_t smem_u32(const void* p) {
    uint32_t a;
    asm("{ .reg .u64 t; cvta.to.shared.u64 t, %1; cvt.u32.u64 %0, t; }" : "=r"(a) : "l"(p));
    return a;
}
#define STS128(r0, r1, r2, r3, addr) \
    asm volatile("st.shared.v4.b32 [%0], {%1, %2, %3, %4};" \
        :: "r"(addr), "r"(r0), "r"(r1), "r"(r2), "r"(r3) : "memory")
#define LDSM4(r, addr) \
    asm volatile("ldmatrix.sync.aligned.m8n8.x4.shared.b16 {%0,%1,%2,%3}, [%4];" \
        : "=r"((r)[0]), "=r"((r)[1]), "=r"((r)[2]), "=r"((r)[3]) : "r"(addr))
#define MMA_BF16(d, a, b0, b1) \
    asm volatile("mma.sync.aligned.m16n8k16.row.col.f32.bf16.bf16.f32 " \
        "{%0,%1,%2,%3}, {%4,%5,%6,%7}, {%8,%9}, {%0,%1,%2,%3};" \
        : "+f"((d)[0]), "+f"((d)[1]), "+f"((d)[2]), "+f"((d)[3]) \
        : "r"((a)[0]), "r"((a)[1]), "r"((a)[2]), "r"((a)[3]), "r"(b0), "r"(b1))
#define CP_ASYNC16(dst, src) \
    asm volatile("cp.async.cg.shared.global [%0], [%1], 16;" :: "r"(dst), "l"(src) : "memory")
#define CP_COMMIT() asm volatile("cp.async.commit_group;" ::: "memory")
#define CP_WAIT(n)  asm volatile("cp.async.wait_group %0;" :: "n"(n) : "memory")
#define SWZ128(off) ((uint32_t)(off) ^ ((((uint32_t)(off)) >> 3) & 0x70u))

// ---- dynamic smem layout (bytes) ----
// A: [part(2)][khrow(4)] planes of 130 px x 64 ci bf16 (SW128), plane padded to 17408
// B: single buffer [kw(3)][part(2)] tiles of 64co x 64ci bf16 (SW128, 8192 B each)
// stats: 64 mean + 64 rstd floats
#define PLANE 17408
#define SMB_OFF (8 * PLANE)            // 139264
#define SMB_SZ  49152
#define SM_STAT (SMB_OFF + SMB_SZ)     // 188416
#define SMEM_TOTAL (SM_STAT + 512)     // 188928

// ======================= weight prep: fp32 -> split bf16 ================
// dst layout: [b][tap(kh*3+kw)][co][ci]
__global__ void prep_w_kernel(const float* __restrict__ k1, const float* __restrict__ k2) {
    int gi = blockIdx.x * 256 + threadIdx.x;
    if (gi >= 2 * WSZ) return;
    const float* src; __nv_bfloat16 *dh, *dl; int i;
    if (gi < WSZ) { src = k1; dh = g_w1h; dl = g_w1l; i = gi; }
    else          { src = k2; dh = g_w2h; dl = g_w2l; i = gi - WSZ; }
    int ci = i & 63;
    int co = (i >> 6) & 63;
    int k9 = (i >> 12) % 9;
    int b  = (i >> 12) / 9;
    float w = src[(((b * 64 + co) * 64 + ci) * 9) + k9];
    __nv_bfloat16 h = __float2bfloat16(w);
    __nv_bfloat16 l = __float2bfloat16(w - __bfloat162float(h));
    dh[i] = h; dl[i] = l;
}

// ======================= conv via mma.sync bf16 split ===================
// CTA = (row-pair y0=2*bx, batch b). Two output rows share 4 staged kh-rows
// and one B load. 8 warps = 2 rows x 4 M-tiles; warp tile = 32 px x 64 co.
template<int PASS>
__global__ __launch_bounds__(256, 1)
void conv_mma_kernel(const float* __restrict__ x_ext) {
    extern __shared__ __align__(1024) char smem[];
    const uint32_t sb = smem_u32(smem);
    const int tid = threadIdx.x, lid = tid & 31, wid = tid >> 5;
    const int y0 = blockIdx.x * 2, b = blockIdx.y;
    const float* src = (PASS == 0) ? x_ext : g_buf1;
    const __nv_bfloat16* wh = (PASS == 0) ? g_w1h : g_w2h;
    const __nv_bfloat16* wl = (PASS == 0) ? g_w1l : g_w2l;
    float* dst = (PASS == 0) ? g_buf1 : g_buf2;

    float* smean = (float*)(smem + SM_STAT);
    float* srstd = smean + 64;

    if (PASS == 1) {
        if (tid < 64) {
            smean[tid] = g_mean[b * 64 + tid];
            srstd[tid] = g_rstd[b * 64 + tid];
        }
        __syncthreads();
    }

    // ---------- stage A: 4 kh-rows x 130 px x 64 ci, hi+lo ----------
    {
        const int px = tid & 127;
        const int cihalf = (tid >> 7) * 32;
        const int ar = px + 1;
#pragma unroll
        for (int krow = 0; krow < 4; ++krow) {
            const int grow = y0 + krow - 1;
            const bool vr = (unsigned)grow < 128u;
            const float* base = src + (size_t)b * CHW + (size_t)(vr ? grow : 0) * WW + px;
            const uint32_t ph = sb + (0 * 4 + krow) * PLANE;
            const uint32_t pl = sb + (1 * 4 + krow) * PLANE;
#pragma unroll
            for (int c8 = 0; c8 < 4; ++c8) {
                const int ci0 = cihalf + c8 * 8;
                float v[8];
#pragma unroll
                for (int j = 0; j < 8; ++j) {
                    float t = vr ? __ldg(base + (size_t)(ci0 + j) * HWD) : 0.f;
                    if (PASS == 1 && vr) {
                        t = (t - smean[ci0 + j]) * srstd[ci0 + j];
                        t = t >= 0.f ? t : 0.2f * t;
                    }
                    v[j] = t;
                }
                uint32_t hp[4], lp[4];
#pragma unroll
                for (int j = 0; j < 4; ++j) {
                    __nv_bfloat16 h0 = __float2bfloat16(v[2*j]);
                    __nv_bfloat16 h1 = __float2bfloat16(v[2*j+1]);
                    __nv_bfloat16 l0 = __float2bfloat16(v[2*j]   - __bfloat162float(h0));
                    __nv_bfloat16 l1 = __float2bfloat16(v[2*j+1] - __bfloat162float(h1));
                    hp[j] = (uint32_t)__bfloat16_as_ushort(h0) | ((uint32_t)__bfloat16_as_ushort(h1) << 16);
                    lp[j] = (uint32_t)__bfloat16_as_ushort(l0) | ((uint32_t)__bfloat16_as_ushort(l1) << 16);
                }
                const uint32_t off = SWZ128(ar * 128 + ci0 * 2);
                STS128(hp[0], hp[1], hp[2], hp[3], ph + off);
                STS128(lp[0], lp[1], lp[2], lp[3], pl + off);
            }
        }
        // zero halo rows ar=0 and ar=129 of all 8 planes
        if (tid < 128) {
            const int plane = tid >> 4;
            const int row = (tid & 8) ? 129 : 0;
            const int chunk = tid & 7;
            const uint32_t off = SWZ128(row * 128 + chunk * 16);
            STS128(0u, 0u, 0u, 0u, sb + plane * PLANE + off);
        }
    }

    // ---------- warp tiling ----------
    const int rowsel = wid >> 2;            // output row within pair
    const int m0 = (wid & 3) * 32;          // px base
    const int la_row = lid & 15;
    const int la_k   = (lid & 16) ? 8 : 0;
    const int lb_n   = (lid & 7) + ((lid & 16) ? 8 : 0);
    const int lb_k   = (lid & 8);

    float acc[2][8][4];
#pragma unroll
    for (int mt = 0; mt < 2; ++mt)
#pragma unroll
        for (int nt = 0; nt < 8; ++nt)
#pragma unroll
            for (int j = 0; j < 4; ++j) acc[mt][nt][j] = 0.f;

    for (int kh = 0; kh < 3; ++kh) {
        // stage B(kh): 12 cp.async per thread (48 KB)
        {
#pragma unroll
            for (int kw = 0; kw < 3; ++kw) {
#pragma unroll
                for (int part = 0; part < 2; ++part) {
                    const __nv_bfloat16* s = (part ? wl : wh)
                        + (size_t)(b * 9 + kh * 3 + kw) * 4096;
                    const uint32_t dstb = sb + SMB_OFF + (kw * 2 + part) * 8192;
#pragma unroll
                    for (int i = 0; i < 2; ++i) {
                        const int chunk = i * 256 + tid;   // 0..511 (16B units)
                        CP_ASYNC16(dstb + SWZ128(chunk * 16), s + chunk * 8);
                    }
                }
            }
        }
        CP_COMMIT(); CP_WAIT(0);
        __syncthreads();   // B(kh) visible; first iter also covers A staging

#pragma unroll
        for (int term = 0; term < 3; ++term) {
            const int ap = (term == 1) ? 1 : 0;
            const int bp = (term == 2) ? 1 : 0;
            const uint32_t aplane = sb + (ap * 4 + rowsel + kh) * PLANE;
#pragma unroll
            for (int kw = 0; kw < 3; ++kw) {
                const uint32_t btile = sb + SMB_OFF + (kw * 2 + bp) * 8192;
#pragma unroll
                for (int kt = 0; kt < 4; ++kt) {
                    uint32_t af[2][4];
#pragma unroll
                    for (int mt = 0; mt < 2; ++mt) {
                        const uint32_t off = (uint32_t)((m0 + mt * 16 + la_row + kw) * 128
                                                        + (kt * 16 + la_k) * 2);
                        LDSM4(af[mt], aplane + SWZ128(off));
                    }
                    uint32_t bf[4][4];
#pragma unroll
                    for (int nt2 = 0; nt2 < 4; ++nt2) {
                        const uint32_t off = (uint32_t)((nt2 * 16 + lb_n) * 128
                                                        + (kt * 16 + lb_k) * 2);
                        LDSM4(bf[nt2], btile + SWZ128(off));
                    }
#pragma unroll
                    for (int mt = 0; mt < 2; ++mt) {
#pragma unroll
                        for (int nt2 = 0; nt2 < 4; ++nt2) {
                            MMA_BF16(acc[mt][nt2 * 2],     af[mt], bf[nt2][0], bf[nt2][1]);
                            MMA_BF16(acc[mt][nt2 * 2 + 1], af[mt], bf[nt2][2], bf[nt2][3]);
                        }
                    }
                }
            }
        }
        __syncthreads();   // done reading B before restage (and A before epilogue)
    }

    // ---------- epilogue: acc -> smem D[2][64][132] -> coalesced gmem ----------
    float* D = (float*)smem;    // aliases A region (all reads done)
    {
        const int pr = lid >> 2, qc = 2 * (lid & 3);
#pragma unroll
        for (int mt = 0; mt < 2; ++mt) {
#pragma unroll
            for (int nt = 0; nt < 8; ++nt) {
                const int px = m0 + mt * 16 + pr;
                const int co = nt * 8 + qc;
                float* dr = D + (size_t)(rowsel * 64 + co) * 132;
                dr[px]            = acc[mt][nt][0];
                dr[132 + px]      = acc[mt][nt][1];
                dr[px + 8]        = acc[mt][nt][2];
                dr[132 + px + 8]  = acc[mt][nt][3];
            }
        }
    }
    __syncthreads();
    {
        const int co = tid >> 2;
        const int pxb = (tid & 3) * 32;
#pragma unroll
        for (int r = 0; r < 2; ++r) {
            float* op = dst + (size_t)b * CHW + (size_t)co * HWD + (y0 + r) * WW + pxb;
            const float* dr = D + (size_t)(r * 64 + co) * 132 + pxb;
#pragma unroll
            for (int i = 0; i < 8; ++i) {
                *(float4*)(op + i * 4) = *(const float4*)(dr + i * 4);
            }
        }
    }
}

// ======================= instance-norm stats =======================
template<int PASS>
__global__ void stats_kernel() {
    const float* buf = (PASS == 0) ? g_buf1 : g_buf2;
    const int g = blockIdx.x;
    const float4* p = (const float4*)(buf + (size_t)g * HWD);
    float s = 0.f, s2 = 0.f;
    for (int i = threadIdx.x; i < HWD / 4; i += 256) {
        float4 v = p[i];
        s  += v.x + v.y + v.z + v.w;
        s2 += v.x * v.x + v.y * v.y + v.z * v.z + v.w * v.w;
    }
#pragma unroll
    for (int o = 16; o; o >>= 1) {
        s  += __shfl_xor_sync(0xffffffffu, s, o);
        s2 += __shfl_xor_sync(0xffffffffu, s2, o);
    }
    __shared__ float ss[8], ss2[8];
    int w = threadIdx.x >> 5, l = threadIdx.x & 31;
    if (l == 0) { ss[w] = s; ss2[w] = s2; }
    __syncthreads();
    if (threadIdx.x == 0) {
        float t = 0.f, t2 = 0.f;
#pragma unroll
        for (int i = 0; i < 8; ++i) { t += ss[i]; t2 += ss2[i]; }
        const float inv = 1.f / (float)HWD;
        float m = t * inv;
        float var = t2 * inv - m * m;
        g_mean[g] = m;
        g_rstd[g] = rsqrtf(var + 1e-5f);
    }
}

__device__ __forceinline__ float lrelu(float v) { return v >= 0.f ? v : 0.2f * v; }

// ---------- out = lrelu(x + IN(buf2)) ----------
__global__ void final_kernel(const float* __restrict__ x, float* __restrict__ out) {
    const int i = blockIdx.x * 256 + threadIdx.x;      // float4 index
    float4 v  = ((const float4*)g_buf2)[i];
    float4 xv = ((const float4*)x)[i];
    const int g = i >> 12;
    const float m = g_mean[g], rs = g_rstd[g];
    float4 o;
    o.x = lrelu(xv.x + (v.x - m) * rs);
    o.y = lrelu(xv.y + (v.y - m) * rs);
    o.z = lrelu(xv.z + (v.z - m) * rs);
    o.w = lrelu(xv.w + (v.w - m) * rs);
    ((float4*)out)[i] = o;
}

extern "C" void kernel_launch(void* const* d_in, const int* in_sizes, int n_in,
                              void* d_out, int out_size) {
    const float* x  = (const float*)d_in[0];
    const float* k1 = (const float*)d_in[1];
    const float* k2 = (const float*)d_in[2];
    float* out = (float*)d_out;

    cudaFuncSetAttribute(conv_mma_kernel<0>, cudaFuncAttributeMaxDynamicSharedMemorySize, SMEM_TOTAL);
    cudaFuncSetAttribute(conv_mma_kernel<1>, cudaFuncAttributeMaxDynamicSharedMemorySize, SMEM_TOTAL);

    prep_w_kernel<<<(2 * WSZ + 255) / 256, 256>>>(k1, k2);

    dim3 grid(HH / 2, BB);   // (row-pair, batch)
    conv_mma_kernel<0><<<grid, 256, SMEM_TOTAL>>>(x);
    stats_kernel<0><<<NGRP, 256>>>();
    conv_mma_kernel<1><<<grid, 256, SMEM_TOTAL>>>(x);
    stats_kernel<1><<<NGRP, 256>>>();
    final_kernel<<<NELEM / 1024, 256>>>(x, out);
}

// round 7
// speedup vs baseline: 3.7935x; 1.2705x over previous
#include <cuda_runtime.h>
#include <cuda_bf16.h>
#include <cstdint>

#define BB 16
#define CC 64
#define HH 128
#define WW 128
#define HWD (HH*WW)            // 16384
#define CHW (CC*HWD)           // 1048576
#define NELEM (BB*CHW)         // 16777216
#define NGRP (BB*CC)           // 1024
#define WSZ (BB*CC*CC*9)       // 589824

// Scratch (device globals: allocation-free rule)
__device__ float g_buf1[NELEM];
__device__ float g_buf2[NELEM];
__device__ __align__(16) __nv_bfloat16 g_w1h[WSZ];
__device__ __align__(16) __nv_bfloat16 g_w1l[WSZ];
__device__ __align__(16) __nv_bfloat16 g_w2h[WSZ];
__device__ __align__(16) __nv_bfloat16 g_w2l[WSZ];
__device__ float g_mean[NGRP];
__device__ float g_rstd[NGRP];
__device__ float g_psum[NGRP * 64];    // [group][rowpair]
__device__ float g_psum2[NGRP * 64];

// ======================= PTX helpers (plain compute_103-safe) ==========
__device__ __forceinline__ uint32_t smem_u32(const void* p) {
    uint32_t a;
    asm("{ .reg .u64 t; cvta.to.shared.u64 t, %1; cvt.u32.u64 %0, t; }" : "=r"(a) : "l"(p));
    return a;
}
#define STS128(r0, r1, r2, r3, addr) \
    asm volatile("st.shared.v4.b32 [%0], {%1, %2, %3, %4};" \
        :: "r"(addr), "r"(r0), "r"(r1), "r"(r2), "r"(r3) : "memory")
#define LDSM4(r, addr) \
    asm volatile("ldmatrix.sync.aligned.m8n8.x4.shared.b16 {%0,%1,%2,%3}, [%4];" \
        : "=r"((r)[0]), "=r"((r)[1]), "=r"((r)[2]), "=r"((r)[3]) : "r"(addr))
#define MMA_BF16(d, a, b0, b1) \
    asm volatile("mma.sync.aligned.m16n8k16.row.col.f32.bf16.bf16.f32 " \
        "{%0,%1,%2,%3}, {%4,%5,%6,%7}, {%8,%9}, {%0,%1,%2,%3};" \
        : "+f"((d)[0]), "+f"((d)[1]), "+f"((d)[2]), "+f"((d)[3]) \
        : "r"((a)[0]), "r"((a)[1]), "r"((a)[2]), "r"((a)[3]), "r"(b0), "r"(b1))
#define CP_ASYNC16(dst, src) \
    asm volatile("cp.async.cg.shared.global [%0], [%1], 16;" :: "r"(dst), "l"(src) : "memory")
#define CP_COMMIT() asm volatile("cp.async.commit_group;" ::: "memory")
#define CP_WAIT(n)  asm volatile("cp.async.wait_group %0;" :: "n"(n) : "memory")
#define SWZ128(off) ((uint32_t)(off) ^ ((((uint32_t)(off)) >> 3) & 0x70u))

// ---- dynamic smem layout (bytes) ----
#define PLANE 17408
#define SMB_OFF (8 * PLANE)            // 139264
#define SMB_SZ  49152
#define SM_STAT (SMB_OFF + SMB_SZ)     // 188416  (mean[64] + rstd[64] = 512 B)
#define SM_PART (SM_STAT + 512)        // 188928  (partials: 256 floats = 1024 B)
#define SMEM_TOTAL (SM_PART + 1024)    // 189952  (< 227 KB cap)

// ======================= weight prep: fp32 -> split bf16 ================
// dst layout: [b][tap(kh*3+kw)][co][ci]
__global__ void prep_w_kernel(const float* __restrict__ k1, const float* __restrict__ k2) {
    int gi = blockIdx.x * 256 + threadIdx.x;
    if (gi >= 2 * WSZ) return;
    const float* src; __nv_bfloat16 *dh, *dl; int i;
    if (gi < WSZ) { src = k1; dh = g_w1h; dl = g_w1l; i = gi; }
    else          { src = k2; dh = g_w2h; dl = g_w2l; i = gi - WSZ; }
    int ci = i & 63;
    int co = (i >> 6) & 63;
    int k9 = (i >> 12) % 9;
    int b  = (i >> 12) / 9;
    float w = src[(((b * 64 + co) * 64 + ci) * 9) + k9];
    __nv_bfloat16 h = __float2bfloat16(w);
    __nv_bfloat16 l = __float2bfloat16(w - __bfloat162float(h));
    dh[i] = h; dl[i] = l;
}

// ======================= conv via mma.sync bf16 split ===================
// CTA = (row-pair, batch). 8 warps = 2 rows x 4 M-tiles; warp 32px x 64co.
// Per (kw,kt): 12 LDSM (af hi/lo + bf hi/lo) feed 48 MMAs (hh, lh, hl).
template<int PASS>
__global__ __launch_bounds__(256, 1)
void conv_mma_kernel(const float* __restrict__ x_ext) {
    extern __shared__ __align__(1024) char smem[];
    const uint32_t sb = smem_u32(smem);
    const int tid = threadIdx.x, lid = tid & 31, wid = tid >> 5;
    const int rp = blockIdx.x, y0 = rp * 2, b = blockIdx.y;
    const float* src = (PASS == 0) ? x_ext : g_buf1;
    const __nv_bfloat16* wh = (PASS == 0) ? g_w1h : g_w2h;
    const __nv_bfloat16* wl = (PASS == 0) ? g_w1l : g_w2l;
    float* dst = (PASS == 0) ? g_buf1 : g_buf2;

    float* smean = (float*)(smem + SM_STAT);
    float* srstd = smean + 64;

    if (PASS == 1) {
        if (tid < 64) {
            smean[tid] = g_mean[b * 64 + tid];
            srstd[tid] = g_rstd[b * 64 + tid];
        }
        __syncthreads();
    }

    // ---------- stage A: 4 kh-rows x 130 px x 64 ci, hi+lo ----------
    {
        const int px = tid & 127;
        const int cihalf = (tid >> 7) * 32;
        const int ar = px + 1;
#pragma unroll
        for (int krow = 0; krow < 4; ++krow) {
            const int grow = y0 + krow - 1;
            const bool vr = (unsigned)grow < 128u;
            const float* base = src + (size_t)b * CHW + (size_t)(vr ? grow : 0) * WW + px;
            const uint32_t ph = sb + (0 * 4 + krow) * PLANE;
            const uint32_t pl = sb + (1 * 4 + krow) * PLANE;
#pragma unroll
            for (int c8 = 0; c8 < 4; ++c8) {
                const int ci0 = cihalf + c8 * 8;
                float v[8];
#pragma unroll
                for (int j = 0; j < 8; ++j) {
                    float t = vr ? __ldg(base + (size_t)(ci0 + j) * HWD) : 0.f;
                    if (PASS == 1 && vr) {
                        t = (t - smean[ci0 + j]) * srstd[ci0 + j];
                        t = t >= 0.f ? t : 0.2f * t;
                    }
                    v[j] = t;
                }
                uint32_t hp[4], lp[4];
#pragma unroll
                for (int j = 0; j < 4; ++j) {
                    __nv_bfloat16 h0 = __float2bfloat16(v[2*j]);
                    __nv_bfloat16 h1 = __float2bfloat16(v[2*j+1]);
                    __nv_bfloat16 l0 = __float2bfloat16(v[2*j]   - __bfloat162float(h0));
                    __nv_bfloat16 l1 = __float2bfloat16(v[2*j+1] - __bfloat162float(h1));
                    hp[j] = (uint32_t)__bfloat16_as_ushort(h0) | ((uint32_t)__bfloat16_as_ushort(h1) << 16);
                    lp[j] = (uint32_t)__bfloat16_as_ushort(l0) | ((uint32_t)__bfloat16_as_ushort(l1) << 16);
                }
                const uint32_t off = SWZ128(ar * 128 + ci0 * 2);
                STS128(hp[0], hp[1], hp[2], hp[3], ph + off);
                STS128(lp[0], lp[1], lp[2], lp[3], pl + off);
            }
        }
        if (tid < 128) {   // zero halo rows ar=0 / ar=129, all 8 planes
            const int plane = tid >> 4;
            const int row = (tid & 8) ? 129 : 0;
            const int chunk = tid & 7;
            STS128(0u, 0u, 0u, 0u, sb + plane * PLANE + SWZ128(row * 128 + chunk * 16));
        }
    }

    // ---------- warp tiling ----------
    const int rowsel = wid >> 2;
    const int m0 = (wid & 3) * 32;
    const int la_row = lid & 15;
    const int la_k   = (lid & 16) ? 8 : 0;
    const int lb_n   = (lid & 7) + ((lid & 16) ? 8 : 0);
    const int lb_k   = (lid & 8);

    float acc[2][8][4];
#pragma unroll
    for (int mt = 0; mt < 2; ++mt)
#pragma unroll
        for (int nt = 0; nt < 8; ++nt)
#pragma unroll
            for (int j = 0; j < 4; ++j) acc[mt][nt][j] = 0.f;

#pragma unroll 1
    for (int kh = 0; kh < 3; ++kh) {
        // stage B(kh): 12 cp.async per thread (48 KB)
#pragma unroll
        for (int kw = 0; kw < 3; ++kw) {
#pragma unroll
            for (int part = 0; part < 2; ++part) {
                const __nv_bfloat16* s = (part ? wl : wh)
                    + (size_t)(b * 9 + kh * 3 + kw) * 4096;
                const uint32_t dstb = sb + SMB_OFF + (kw * 2 + part) * 8192;
#pragma unroll
                for (int i = 0; i < 2; ++i) {
                    const int chunk = i * 256 + tid;
                    CP_ASYNC16(dstb + SWZ128(chunk * 16), s + chunk * 8);
                }
            }
        }
        CP_COMMIT(); CP_WAIT(0);
        __syncthreads();

        const uint32_t aplaneH = sb + (rowsel + kh) * PLANE;
        const uint32_t aplaneL = aplaneH + 4 * PLANE;

#pragma unroll 1
        for (int kw = 0; kw < 3; ++kw) {
            const uint32_t btileH = sb + SMB_OFF + kw * 16384;
            const uint32_t btileL = btileH + 8192;
            const uint32_t arow = (uint32_t)(m0 + la_row + kw) * 128;
#pragma unroll
            for (int kt = 0; kt < 4; ++kt) {
                const uint32_t kcol = (uint32_t)(kt * 16 + la_k) * 2;
                const uint32_t bcol = (uint32_t)(kt * 16 + lb_k) * 2;
                uint32_t afh[2][4], afl[2][4];
#pragma unroll
                for (int mt = 0; mt < 2; ++mt) {
                    const uint32_t off = SWZ128(arow + (uint32_t)(mt * 16) * 128 + kcol);
                    LDSM4(afh[mt], aplaneH + off);
                    LDSM4(afl[mt], aplaneL + off);
                }
                uint32_t bfh[4][4], bfl[4][4];
#pragma unroll
                for (int nt2 = 0; nt2 < 4; ++nt2) {
                    const uint32_t off = SWZ128((uint32_t)(nt2 * 16 + lb_n) * 128 + bcol);
                    LDSM4(bfh[nt2], btileH + off);
                    LDSM4(bfl[nt2], btileL + off);
                }
#pragma unroll
                for (int mt = 0; mt < 2; ++mt) {
#pragma unroll
                    for (int nt2 = 0; nt2 < 4; ++nt2) {
                        // hh
                        MMA_BF16(acc[mt][nt2 * 2],     afh[mt], bfh[nt2][0], bfh[nt2][1]);
                        MMA_BF16(acc[mt][nt2 * 2 + 1], afh[mt], bfh[nt2][2], bfh[nt2][3]);
                        // lh
                        MMA_BF16(acc[mt][nt2 * 2],     afl[mt], bfh[nt2][0], bfh[nt2][1]);
                        MMA_BF16(acc[mt][nt2 * 2 + 1], afl[mt], bfh[nt2][2], bfh[nt2][3]);
                        // hl
                        MMA_BF16(acc[mt][nt2 * 2],     afh[mt], bfl[nt2][0], bfl[nt2][1]);
                        MMA_BF16(acc[mt][nt2 * 2 + 1], afh[mt], bfl[nt2][2], bfl[nt2][3]);
                    }
                }
            }
        }
        __syncthreads();   // done reading B before restage (and A before epilogue)
    }

    // ---------- epilogue: acc -> smem D[2][64][132] -> gmem + IN partials ----
    float* D = (float*)smem;    // aliases A region (all reads done)
    {
        const int pr = lid >> 2, qc = 2 * (lid & 3);
#pragma unroll
        for (int mt = 0; mt < 2; ++mt) {
#pragma unroll
            for (int nt = 0; nt < 8; ++nt) {
                const int px = m0 + mt * 16 + pr;
                const int co = nt * 8 + qc;
                float* dr = D + (size_t)(rowsel * 64 + co) * 132;
                dr[px]            = acc[mt][nt][0];
                dr[132 + px]      = acc[mt][nt][1];
                dr[px + 8]        = acc[mt][nt][2];
                dr[132 + px + 8]  = acc[mt][nt][3];
            }
        }
    }
    __syncthreads();
    {   // coalesced store
        const int co = tid >> 2;
        const int pxb = (tid & 3) * 32;
#pragma unroll
        for (int r = 0; r < 2; ++r) {
            float* op = dst + (size_t)b * CHW + (size_t)co * HWD + (y0 + r) * WW + pxb;
            const float* dr = D + (size_t)(r * 64 + co) * 132 + pxb;
#pragma unroll
            for (int i = 0; i < 8; ++i)
                *(float4*)(op + i * 4) = *(const float4*)(dr + i * 4);
        }
    }
    {   // instance-norm partials: thread t -> (r, co, half)
        const int r = tid >> 7, co = (tid >> 1) & 63, half = tid & 1;
        const float* dr = D + (size_t)(r * 64 + co) * 132 + half * 64;
        float s = 0.f, s2 = 0.f;
#pragma unroll
        for (int i = 0; i < 64; ++i) { float v = dr[i]; s += v; s2 += v * v; }
        s  += __shfl_xor_sync(0xffffffffu, s, 1);
        s2 += __shfl_xor_sync(0xffffffffu, s2, 1);
        if (half == 0) {
            float* P = (float*)(smem + SM_PART);
            P[r * 64 + co]       = s;
            P[128 + r * 64 + co] = s2;
        }
    }
    __syncthreads();
    if (tid < 64) {
        const float* P = (float*)(smem + SM_PART);
        const int g = b * 64 + tid;
        g_psum [g * 64 + rp] = P[tid] + P[64 + tid];
        g_psum2[g * 64 + rp] = P[128 + tid] + P[192 + tid];
    }
}

// ======================= stats reduce: 64 partials per group ============
__global__ void stats_reduce_kernel() {
    const int g = blockIdx.x;
    const int l = threadIdx.x;          // 32 threads
    float s  = g_psum [g * 64 + 2 * l] + g_psum [g * 64 + 2 * l + 1];
    float s2 = g_psum2[g * 64 + 2 * l] + g_psum2[g * 64 + 2 * l + 1];
#pragma unroll
    for (int o = 16; o; o >>= 1) {
        s  += __shfl_xor_sync(0xffffffffu, s, o);
        s2 += __shfl_xor_sync(0xffffffffu, s2, o);
    }
    if (l == 0) {
        const float inv = 1.f / (float)HWD;
        float m = s * inv;
        float var = s2 * inv - m * m;
        g_mean[g] = m;
        g_rstd[g] = rsqrtf(var + 1e-5f);
    }
}

__device__ __forceinline__ float lrelu(float v) { return v >= 0.f ? v : 0.2f * v; }

// ---------- out = lrelu(x + IN(buf2)) ----------
__global__ void final_kernel(const float* __restrict__ x, float* __restrict__ out) {
    const int i = blockIdx.x * 256 + threadIdx.x;      // float4 index
    float4 v  = ((const float4*)g_buf2)[i];
    float4 xv = ((const float4*)x)[i];
    const int g = i >> 12;
    const float m = g_mean[g], rs = g_rstd[g];
    float4 o;
    o.x = lrelu(xv.x + (v.x - m) * rs);
    o.y = lrelu(xv.y + (v.y - m) * rs);
    o.z = lrelu(xv.z + (v.z - m) * rs);
    o.w = lrelu(xv.w + (v.w - m) * rs);
    ((float4*)out)[i] = o;
}

extern "C" void kernel_launch(void* const* d_in, const int* in_sizes, int n_in,
                              void* d_out, int out_size) {
    const float* x  = (const float*)d_in[0];
    const float* k1 = (const float*)d_in[1];
    const float* k2 = (const float*)d_in[2];
    float* out = (float*)d_out;

    cudaFuncSetAttribute(conv_mma_kernel<0>, cudaFuncAttributeMaxDynamicSharedMemorySize, SMEM_TOTAL);
    cudaFuncSetAttribute(conv_mma_kernel<1>, cudaFuncAttributeMaxDynamicSharedMemorySize, SMEM_TOTAL);

    prep_w_kernel<<<(2 * WSZ + 255) / 256, 256>>>(k1, k2);

    dim3 grid(HH / 2, BB);   // (row-pair, batch)
    conv_mma_kernel<0><<<grid, 256, SMEM_TOTAL>>>(x);
    stats_reduce_kernel<<<NGRP, 32>>>();
    conv_mma_kernel<1><<<grid, 256, SMEM_TOTAL>>>(x);
    stats_reduce_kernel<<<NGRP, 32>>>();
    final_kernel<<<NELEM / 1024, 256>>>(x, out);
}